// round 11
// baseline (speedup 1.0000x reference)
#include <cuda_runtime.h>
#include <cuda_bf16.h>
#include <cuda_fp16.h>
#include <cstdint>

#define N_NODES 50000
#define N_EDGES 800000
#define CAP 64
#define LDA 136

// ---------------- scratch (device globals; no allocation allowed) ----------
__device__ int    g_count[N_NODES];           // zero-init; re-zeroed by agg64
__device__ int    g_slot[N_NODES * CAP];
__device__ __half g_zh[N_NODES * 128];        // GEMM output, fp16
__device__ float  g_h[N_NODES * 128];         // agg output, fp32
// packed split weights: per (n, k-pair): {hi[k],hi[k+1]} , {lo[k],lo[k+1]}
// W1: 8192 uint2 | W2: 8192 | W3: 4096
__device__ uint2  g_wp[20480];

// ---------------- small helpers ----------------
__device__ __forceinline__ uint32_t smem_u32(const void* p) {
    uint32_t a;
    asm("{ .reg .u64 t; cvta.to.shared.u64 t, %1; cvt.u32.u64 %0, t; }"
        : "=r"(a) : "l"(p));
    return a;
}

#define LDMATRIX_X4(r, addr) \
    asm volatile("ldmatrix.sync.aligned.m8n8.x4.shared.b16 {%0,%1,%2,%3}, [%4];" \
                 : "=r"((r)[0]), "=r"((r)[1]), "=r"((r)[2]), "=r"((r)[3]) \
                 : "r"(addr))

#define MMA_BF16(acc, a, b0, b1) \
    asm volatile("mma.sync.aligned.m16n8k16.row.col.f32.bf16.bf16.f32 " \
                 "{%0,%1,%2,%3}, {%4,%5,%6,%7}, {%8,%9}, {%0,%1,%2,%3};" \
                 : "+f"((acc)[0]), "+f"((acc)[1]), "+f"((acc)[2]), "+f"((acc)[3]) \
                 : "r"((a)[0]), "r"((a)[1]), "r"((a)[2]), "r"((a)[3]), \
                   "r"(b0), "r"(b1))

__device__ __forceinline__ uint32_t pack_bf162(float a, float b) {
    __nv_bfloat162 p;
    p.x = __float2bfloat16_rn(a);
    p.y = __float2bfloat16_rn(b);
    return *reinterpret_cast<uint32_t*>(&p);
}

// accumulate 8 fp16 values (as uint4) into 8 fp32 accumulators (exact)
__device__ __forceinline__ void add8h(float* acc, uint4 v) {
    const __half2* h = reinterpret_cast<const __half2*>(&v);
    #pragma unroll
    for (int i = 0; i < 4; i++) {
        float2 f = __half22float2(h[i]);
        acc[2 * i]     += f.x;
        acc[2 * i + 1] += f.y;
    }
}

// sum two fp16 rows pairwise in fp16 (1 rounding), flush to fp32
__device__ __forceinline__ void pair_flush(float* acc, uint4 a, uint4 b) {
    const __half2* pa = reinterpret_cast<const __half2*>(&a);
    const __half2* pb = reinterpret_cast<const __half2*>(&b);
    #pragma unroll
    for (int i = 0; i < 4; i++) {
        __half2 s = __hadd2(pa[i], pb[i]);
        float2 f = __half22float2(s);
        acc[2 * i]     += f.x;
        acc[2 * i + 1] += f.y;
    }
}

// ---------------- fill (2 edges/thread) + packed split-W setup -------------
__global__ void fill_setup_kernel(const int* __restrict__ src,
                                  const int* __restrict__ dst,
                                  const float* __restrict__ W1,
                                  const float* __restrict__ W2,
                                  const float* __restrict__ W3) {
    int t = blockIdx.x * blockDim.x + threadIdx.x;
    if (t < 20480) {
        const float* W;
        int rel;
        if (t < 8192)       { W = W1; rel = t; }
        else if (t < 16384) { W = W2; rel = t - 8192; }
        else                { W = W3; rel = t - 16384; }
        int n  = rel >> 6;
        int kp = rel & 63;
        float v0 = W[n * 128 + kp * 2 + 0];
        float v1 = W[n * 128 + kp * 2 + 1];
        __nv_bfloat16 h0 = __float2bfloat16_rn(v0);
        __nv_bfloat16 h1 = __float2bfloat16_rn(v1);
        __nv_bfloat162 hi; hi.x = h0; hi.y = h1;
        uint2 o;
        o.x = *reinterpret_cast<uint32_t*>(&hi);
        o.y = pack_bf162(v0 - __bfloat162float(h0), v1 - __bfloat162float(h1));
        g_wp[t] = o;
    }
    int e = t * 2;
    if (e < N_EDGES) {
        int2 s2 = *reinterpret_cast<const int2*>(src + e);
        int2 d2 = *reinterpret_cast<const int2*>(dst + e);
        int p = atomicAdd(&g_count[d2.x], 1);
        if (p < CAP) g_slot[d2.x * CAP + p] = s2.x;
        p = atomicAdd(&g_count[d2.y], 1);
        if (p < CAP) g_slot[d2.y * CAP + p] = s2.y;
    }
}

// ---------------- mma.sync split-bf16 GEMM: Zh[128-tile][N] = A @ W^T ------
// 256 threads = 8 warps; warp w owns m16-tile w (16 rows), all N columns.
// A: fp32, split to bf16 hi/lo during smem staging.
// D = Ahi*Whi^T + Ahi*Wlo^T + Alo*Whi^T (fp32 acc), output fp16.
template <int N>
__global__ void __launch_bounds__(256, 2) mma_gemm(
    const float* __restrict__ A, const uint2* __restrict__ Wp,
    __half* __restrict__ Zh) {
    constexpr int NT = N / 8;
    extern __shared__ __nv_bfloat16 smem[];
    __nv_bfloat16* Ash = smem;
    __nv_bfloat16* Asl = smem + 128 * LDA;

    const int tid  = threadIdx.x;
    const int wid  = tid >> 5;
    const int lane = tid & 31;
    const int m0   = blockIdx.x * 128;

    for (int t = tid; t < 4096; t += 256) {
        int r = t >> 5;
        int c = (t & 31) << 2;
        int m = m0 + r;
        float4 v = make_float4(0.f, 0.f, 0.f, 0.f);
        if (m < N_NODES)
            v = *reinterpret_cast<const float4*>(A + (size_t)m * 128 + c);
        __nv_bfloat16 h0 = __float2bfloat16_rn(v.x);
        __nv_bfloat16 h1 = __float2bfloat16_rn(v.y);
        __nv_bfloat16 h2 = __float2bfloat16_rn(v.z);
        __nv_bfloat16 h3 = __float2bfloat16_rn(v.w);
        __nv_bfloat162 hp0; hp0.x = h0; hp0.y = h1;
        __nv_bfloat162 hp1; hp1.x = h2; hp1.y = h3;
        uint2 hv, lv;
        hv.x = *reinterpret_cast<uint32_t*>(&hp0);
        hv.y = *reinterpret_cast<uint32_t*>(&hp1);
        lv.x = pack_bf162(v.x - __bfloat162float(h0), v.y - __bfloat162float(h1));
        lv.y = pack_bf162(v.z - __bfloat162float(h2), v.w - __bfloat162float(h3));
        *reinterpret_cast<uint2*>(Ash + r * LDA + c) = hv;
        *reinterpret_cast<uint2*>(Asl + r * LDA + c) = lv;
    }
    __syncthreads();

    float acc[NT][4];
    #pragma unroll
    for (int nt = 0; nt < NT; nt++)
        #pragma unroll
        for (int i = 0; i < 4; i++) acc[nt][i] = 0.0f;

    const int wrow = wid * 16;        // one m16 tile per warp
    const int lrow = lane & 15;
    const int kgrp = (lane >> 4) * 8;
    const int wn   = lane >> 2;
    const int wkp  = lane & 3;

    #pragma unroll
    for (int ks = 0; ks < 8; ks++) {
        const int k0 = ks * 16;
        uint32_t ah[4], al[4];
        uint32_t ad = smem_u32(Ash + (wrow + lrow) * LDA + k0 + kgrp);
        LDMATRIX_X4(ah, ad);
        uint32_t bd = smem_u32(Asl + (wrow + lrow) * LDA + k0 + kgrp);
        LDMATRIX_X4(al, bd);
        #pragma unroll
        for (int nt = 0; nt < NT; nt++) {
            const uint2* wp = Wp + (size_t)(nt * 8 + wn) * 64 + (k0 >> 1) + wkp;
            uint2 p0 = wp[0];
            uint2 p1 = wp[4];
            MMA_BF16(acc[nt], ah, p0.x, p1.x);
            MMA_BF16(acc[nt], ah, p0.y, p1.y);
            MMA_BF16(acc[nt], al, p0.x, p1.x);
        }
    }

    int r0 = m0 + wrow + (lane >> 2);
    #pragma unroll
    for (int nt = 0; nt < NT; nt++) {
        int col = nt * 8 + (lane & 3) * 2;
        if (r0 < N_NODES) {
            __half2 hv = __floats2half2_rn(acc[nt][0], acc[nt][1]);
            *reinterpret_cast<__half2*>(Zh + (size_t)r0 * N + col) = hv;
        }
        if (r0 + 8 < N_NODES) {
            __half2 hv = __floats2half2_rn(acc[nt][2], acc[nt][3]);
            *reinterpret_cast<__half2*>(Zh + (size_t)(r0 + 8) * N + col) = hv;
        }
    }
}

// ---------------- gather + self + inv-scale + relu (fp16 z) ----------------
// Rolling index prefetch, two rows in flight, pairwise fp16 add (1 rounding)
// before the fp32 flush.
__global__ void agg128_kernel(const __half* __restrict__ Z,
                              float* __restrict__ H) {
    int node = (blockIdx.x * blockDim.x + threadIdx.x) >> 5;
    if (node >= N_NODES) return;
    int lane = threadIdx.x & 31;
    int g = lane >> 4;
    int c = lane & 15;

    float acc[8];
    #pragma unroll
    for (int i = 0; i < 8; i++) acc[i] = 0.f;

    if (g == 0) {
        uint4 v = *reinterpret_cast<const uint4*>(Z + (size_t)node * 128 + c * 8);
        add8h(acc, v);
    }

    int cnt = g_count[node];
    int deg = cnt < CAP ? cnt : CAP;
    const int* sl = &g_slot[node * CAP];

    int j = g;
    int i0 = (j < deg)     ? sl[j]     : 0;
    int i1 = (j + 2 < deg) ? sl[j + 2] : 0;
    while (j + 2 < deg) {
        int jn = j + 4;
        int n0 = (jn < deg)     ? sl[jn]     : 0;
        int n1 = (jn + 2 < deg) ? sl[jn + 2] : 0;
        uint4 v0 = *reinterpret_cast<const uint4*>(Z + (size_t)i0 * 128 + c * 8);
        uint4 v1 = *reinterpret_cast<const uint4*>(Z + (size_t)i1 * 128 + c * 8);
        pair_flush(acc, v0, v1);
        j = jn; i0 = n0; i1 = n1;
    }
    if (j < deg) {
        uint4 v = *reinterpret_cast<const uint4*>(Z + (size_t)i0 * 128 + c * 8);
        add8h(acc, v);
    }

    __syncwarp();
    #pragma unroll
    for (int i = 0; i < 8; i++)
        acc[i] += __shfl_down_sync(0xffffffffu, acc[i], 16);

    if (g == 0) {
        float sc = 1.0f / ((float)cnt + 1.0f);
        float4 o0 = make_float4(fmaxf(acc[0] * sc, 0.f), fmaxf(acc[1] * sc, 0.f),
                                fmaxf(acc[2] * sc, 0.f), fmaxf(acc[3] * sc, 0.f));
        float4 o1 = make_float4(fmaxf(acc[4] * sc, 0.f), fmaxf(acc[5] * sc, 0.f),
                                fmaxf(acc[6] * sc, 0.f), fmaxf(acc[7] * sc, 0.f));
        float4* dst = reinterpret_cast<float4*>(H + (size_t)node * 128 + c * 8);
        dst[0] = o0;
        dst[1] = o1;
    }
}

// Final layer: 64-dim fp16 z, fp32 output. Warp = 4 groups of 8 lanes.
// Also re-zeroes g_count for graph-replay determinism.
__global__ void agg64_kernel(const __half* __restrict__ Z,
                             float* __restrict__ out) {
    int node = (blockIdx.x * blockDim.x + threadIdx.x) >> 5;
    if (node >= N_NODES) return;
    int lane = threadIdx.x & 31;
    int g = lane >> 3;
    int c = lane & 7;

    float acc[8];
    #pragma unroll
    for (int i = 0; i < 8; i++) acc[i] = 0.f;

    if (g == 0) {
        uint4 v = *reinterpret_cast<const uint4*>(Z + (size_t)node * 64 + c * 8);
        add8h(acc, v);
    }

    int cnt = g_count[node];
    int deg = cnt < CAP ? cnt : CAP;
    const int* sl = &g_slot[node * CAP];

    int j = g;
    int idx = (j < deg) ? sl[j] : 0;
    while (j < deg) {
        int jn = j + 4;
        int idxn = (jn < deg) ? sl[jn] : 0;
        uint4 v = *reinterpret_cast<const uint4*>(Z + (size_t)idx * 64 + c * 8);
        add8h(acc, v);
        j = jn; idx = idxn;
    }

    __syncwarp();
    #pragma unroll
    for (int i = 0; i < 8; i++)
        acc[i] += __shfl_down_sync(0xffffffffu, acc[i], 16);
    #pragma unroll
    for (int i = 0; i < 8; i++)
        acc[i] += __shfl_down_sync(0xffffffffu, acc[i], 8);

    if (lane < 8) {
        float sc = 1.0f / ((float)cnt + 1.0f);
        float4 o0 = make_float4(fmaxf(acc[0] * sc, 0.f), fmaxf(acc[1] * sc, 0.f),
                                fmaxf(acc[2] * sc, 0.f), fmaxf(acc[3] * sc, 0.f));
        float4 o1 = make_float4(fmaxf(acc[4] * sc, 0.f), fmaxf(acc[5] * sc, 0.f),
                                fmaxf(acc[6] * sc, 0.f), fmaxf(acc[7] * sc, 0.f));
        float4* dst = reinterpret_cast<float4*>(out + (size_t)node * 64 + c * 8);
        dst[0] = o0;
        dst[1] = o1;
    }
    if (lane == 0) g_count[node] = 0;   // reset for next launch / replay
}

// ---------------- launch ----------------
extern "C" void kernel_launch(void* const* d_in, const int* in_sizes, int n_in,
                              void* d_out, int out_size) {
    const float* x   = (const float*)d_in[0];
    const int*   ei  = (const int*)d_in[1];
    const float* W1  = (const float*)d_in[2];
    const float* W2  = (const float*)d_in[3];
    const float* W3  = (const float*)d_in[4];
    float*       out = (float*)d_out;

    const int* src = ei;
    const int* dst = ei + N_EDGES;

    __half* zh = nullptr;
    float*  h  = nullptr;
    uint2*  wp = nullptr;
    cudaGetSymbolAddress((void**)&zh, g_zh);
    cudaGetSymbolAddress((void**)&h,  g_h);
    cudaGetSymbolAddress((void**)&wp, g_wp);

    constexpr int SMEM_A = 2 * 128 * LDA * 2;   // 69632 bytes
    cudaFuncSetAttribute(mma_gemm<128>,
                         cudaFuncAttributeMaxDynamicSharedMemorySize, SMEM_A);
    cudaFuncSetAttribute(mma_gemm<64>,
                         cudaFuncAttributeMaxDynamicSharedMemorySize, SMEM_A);

    const int TPB = 256;
    const int gemm_blocks = (N_NODES + 127) / 128;             // 391
    const int agg_blocks  = (N_NODES * 32 + TPB - 1) / TPB;    // 6250
    const int fill_blocks = (N_EDGES / 2 + TPB - 1) / TPB;     // 1563

    fill_setup_kernel<<<fill_blocks, TPB>>>(src, dst, W1, W2, W3);

    // layer 1
    mma_gemm<128><<<gemm_blocks, 256, SMEM_A>>>(x, wp, zh);
    agg128_kernel<<<agg_blocks, TPB>>>(zh, h);
    // layer 2
    mma_gemm<128><<<gemm_blocks, 256, SMEM_A>>>(h, wp + 8192, zh);
    agg128_kernel<<<agg_blocks, TPB>>>(zh, h);
    // layer 3 (N=64), final relu + write out
    mma_gemm<64><<<gemm_blocks, 256, SMEM_A>>>(h, wp + 16384, zh);
    agg64_kernel<<<agg_blocks, TPB>>>(zh, out);
}

// round 12
// speedup vs baseline: 1.1526x; 1.1526x over previous
#include <cuda_runtime.h>
#include <cuda_bf16.h>
#include <cuda_fp16.h>
#include <cstdint>

#define N_NODES 50000
#define N_EDGES 800000
#define CAP 64
#define LDA 136

// ---------------- scratch (device globals; no allocation allowed) ----------
__device__ int    g_count[N_NODES];           // zero-init; re-zeroed by agg64
__device__ int    g_slot[N_NODES * CAP];
__device__ __half g_zh[N_NODES * 128];        // GEMM output, fp16
__device__ float  g_h[N_NODES * 128];         // agg output, fp32
// packed split weights: per (n, k-pair): {hi[k],hi[k+1]} , {lo[k],lo[k+1]}
// W1: 8192 uint2 | W2: 8192 | W3: 4096
__device__ uint2  g_wp[20480];

// ---------------- small helpers ----------------
__device__ __forceinline__ uint32_t smem_u32(const void* p) {
    uint32_t a;
    asm("{ .reg .u64 t; cvta.to.shared.u64 t, %1; cvt.u32.u64 %0, t; }"
        : "=r"(a) : "l"(p));
    return a;
}

#define LDMATRIX_X4(r, addr) \
    asm volatile("ldmatrix.sync.aligned.m8n8.x4.shared.b16 {%0,%1,%2,%3}, [%4];" \
                 : "=r"((r)[0]), "=r"((r)[1]), "=r"((r)[2]), "=r"((r)[3]) \
                 : "r"(addr))

#define MMA_BF16(acc, a, b0, b1) \
    asm volatile("mma.sync.aligned.m16n8k16.row.col.f32.bf16.bf16.f32 " \
                 "{%0,%1,%2,%3}, {%4,%5,%6,%7}, {%8,%9}, {%0,%1,%2,%3};" \
                 : "+f"((acc)[0]), "+f"((acc)[1]), "+f"((acc)[2]), "+f"((acc)[3]) \
                 : "r"((a)[0]), "r"((a)[1]), "r"((a)[2]), "r"((a)[3]), \
                   "r"(b0), "r"(b1))

__device__ __forceinline__ uint32_t pack_bf162(float a, float b) {
    __nv_bfloat162 p;
    p.x = __float2bfloat16_rn(a);
    p.y = __float2bfloat16_rn(b);
    return *reinterpret_cast<uint32_t*>(&p);
}

// accumulate 8 fp16 values (as uint4) into 8 fp32 accumulators (exact)
__device__ __forceinline__ void add8h(float* acc, uint4 v) {
    const __half2* h = reinterpret_cast<const __half2*>(&v);
    #pragma unroll
    for (int i = 0; i < 4; i++) {
        float2 f = __half22float2(h[i]);
        acc[2 * i]     += f.x;
        acc[2 * i + 1] += f.y;
    }
}

// sum two fp16 rows pairwise in fp16 (1 rounding), flush to fp32
__device__ __forceinline__ void pair_flush(float* acc, uint4 a, uint4 b) {
    const __half2* pa = reinterpret_cast<const __half2*>(&a);
    const __half2* pb = reinterpret_cast<const __half2*>(&b);
    #pragma unroll
    for (int i = 0; i < 4; i++) {
        __half2 s = __hadd2(pa[i], pb[i]);
        float2 f = __half22float2(s);
        acc[2 * i]     += f.x;
        acc[2 * i + 1] += f.y;
    }
}

// ---------------- fill (2 edges/thread) + packed split-W setup -------------
__global__ void fill_setup_kernel(const int* __restrict__ src,
                                  const int* __restrict__ dst,
                                  const float* __restrict__ W1,
                                  const float* __restrict__ W2,
                                  const float* __restrict__ W3) {
    int t = blockIdx.x * blockDim.x + threadIdx.x;
    if (t < 20480) {
        const float* W;
        int rel;
        if (t < 8192)       { W = W1; rel = t; }
        else if (t < 16384) { W = W2; rel = t - 8192; }
        else                { W = W3; rel = t - 16384; }
        int n  = rel >> 6;
        int kp = rel & 63;
        float v0 = W[n * 128 + kp * 2 + 0];
        float v1 = W[n * 128 + kp * 2 + 1];
        __nv_bfloat16 h0 = __float2bfloat16_rn(v0);
        __nv_bfloat16 h1 = __float2bfloat16_rn(v1);
        __nv_bfloat162 hi; hi.x = h0; hi.y = h1;
        uint2 o;
        o.x = *reinterpret_cast<uint32_t*>(&hi);
        o.y = pack_bf162(v0 - __bfloat162float(h0), v1 - __bfloat162float(h1));
        g_wp[t] = o;
    }
    int e = t * 2;
    if (e < N_EDGES) {
        int2 s2 = *reinterpret_cast<const int2*>(src + e);
        int2 d2 = *reinterpret_cast<const int2*>(dst + e);
        int p = atomicAdd(&g_count[d2.x], 1);
        if (p < CAP) g_slot[d2.x * CAP + p] = s2.x;
        p = atomicAdd(&g_count[d2.y], 1);
        if (p < CAP) g_slot[d2.y * CAP + p] = s2.y;
    }
}

// ---------------- mma.sync split-bf16 GEMM: Zh[128-tile][N] = A @ W^T ------
// 512 threads = 16 warps; warp = (m16-tile wid>>1, column half wid&1).
// Each warp: 16 rows x N/2 cols -> acc = (N/16)x4 regs. No spills.
// D = Ahi*Whi^T + Ahi*Wlo^T + Alo*Whi^T (fp32 acc), output fp16.
template <int N>
__global__ void __launch_bounds__(512, 2) mma_gemm(
    const float* __restrict__ A, const uint2* __restrict__ Wp,
    __half* __restrict__ Zh) {
    constexpr int NTW = N / 16;      // n-tiles per warp (half of N/8)
    extern __shared__ __nv_bfloat16 smem[];
    __nv_bfloat16* Ash = smem;
    __nv_bfloat16* Asl = smem + 128 * LDA;

    const int tid  = threadIdx.x;
    const int wid  = tid >> 5;
    const int lane = tid & 31;
    const int m0   = blockIdx.x * 128;

    for (int t = tid; t < 4096; t += 512) {
        int r = t >> 5;
        int c = (t & 31) << 2;
        int m = m0 + r;
        float4 v = make_float4(0.f, 0.f, 0.f, 0.f);
        if (m < N_NODES)
            v = *reinterpret_cast<const float4*>(A + (size_t)m * 128 + c);
        __nv_bfloat16 h0 = __float2bfloat16_rn(v.x);
        __nv_bfloat16 h1 = __float2bfloat16_rn(v.y);
        __nv_bfloat16 h2 = __float2bfloat16_rn(v.z);
        __nv_bfloat16 h3 = __float2bfloat16_rn(v.w);
        __nv_bfloat162 hp0; hp0.x = h0; hp0.y = h1;
        __nv_bfloat162 hp1; hp1.x = h2; hp1.y = h3;
        uint2 hv, lv;
        hv.x = *reinterpret_cast<uint32_t*>(&hp0);
        hv.y = *reinterpret_cast<uint32_t*>(&hp1);
        lv.x = pack_bf162(v.x - __bfloat162float(h0), v.y - __bfloat162float(h1));
        lv.y = pack_bf162(v.z - __bfloat162float(h2), v.w - __bfloat162float(h3));
        *reinterpret_cast<uint2*>(Ash + r * LDA + c) = hv;
        *reinterpret_cast<uint2*>(Asl + r * LDA + c) = lv;
    }
    __syncthreads();

    float acc[NTW][4];
    #pragma unroll
    for (int nt = 0; nt < NTW; nt++)
        #pragma unroll
        for (int i = 0; i < 4; i++) acc[nt][i] = 0.0f;

    const int wtile = wid >> 1;       // m16 tile 0..7
    const int chalf = wid & 1;        // column half 0..1
    const int lrow = lane & 15;
    const int kgrp = (lane >> 4) * 8;
    const int wn   = lane >> 2;
    const int wkp  = lane & 3;

    #pragma unroll
    for (int ks = 0; ks < 8; ks++) {
        const int k0 = ks * 16;
        uint32_t ah[4], al[4];
        uint32_t ad = smem_u32(Ash + (wtile * 16 + lrow) * LDA + k0 + kgrp);
        LDMATRIX_X4(ah, ad);
        uint32_t bd = smem_u32(Asl + (wtile * 16 + lrow) * LDA + k0 + kgrp);
        LDMATRIX_X4(al, bd);
        #pragma unroll
        for (int nt = 0; nt < NTW; nt++) {
            int ntg = chalf * NTW + nt;
            const uint2* wp = Wp + (size_t)(ntg * 8 + wn) * 64 + (k0 >> 1) + wkp;
            uint2 p0 = wp[0];
            uint2 p1 = wp[4];
            MMA_BF16(acc[nt], ah, p0.x, p1.x);
            MMA_BF16(acc[nt], ah, p0.y, p1.y);
            MMA_BF16(acc[nt], al, p0.x, p1.x);
        }
    }

    int r0 = m0 + wtile * 16 + (lane >> 2);
    #pragma unroll
    for (int nt = 0; nt < NTW; nt++) {
        int col = (chalf * NTW + nt) * 8 + (lane & 3) * 2;
        if (r0 < N_NODES) {
            __half2 hv = __floats2half2_rn(acc[nt][0], acc[nt][1]);
            *reinterpret_cast<__half2*>(Zh + (size_t)r0 * N + col) = hv;
        }
        if (r0 + 8 < N_NODES) {
            __half2 hv = __floats2half2_rn(acc[nt][2], acc[nt][3]);
            *reinterpret_cast<__half2*>(Zh + (size_t)(r0 + 8) * N + col) = hv;
        }
    }
}

// ---------------- gather + self + inv-scale + relu (fp16 z) ----------------
// Rolling index prefetch, two rows in flight, pairwise fp16 add (1 rounding)
// before the fp32 flush.
__global__ void agg128_kernel(const __half* __restrict__ Z,
                              float* __restrict__ H) {
    int node = (blockIdx.x * blockDim.x + threadIdx.x) >> 5;
    if (node >= N_NODES) return;
    int lane = threadIdx.x & 31;
    int g = lane >> 4;
    int c = lane & 15;

    float acc[8];
    #pragma unroll
    for (int i = 0; i < 8; i++) acc[i] = 0.f;

    if (g == 0) {
        uint4 v = *reinterpret_cast<const uint4*>(Z + (size_t)node * 128 + c * 8);
        add8h(acc, v);
    }

    int cnt = g_count[node];
    int deg = cnt < CAP ? cnt : CAP;
    const int* sl = &g_slot[node * CAP];

    int j = g;
    int i0 = (j < deg)     ? sl[j]     : 0;
    int i1 = (j + 2 < deg) ? sl[j + 2] : 0;
    while (j + 2 < deg) {
        int jn = j + 4;
        int n0 = (jn < deg)     ? sl[jn]     : 0;
        int n1 = (jn + 2 < deg) ? sl[jn + 2] : 0;
        uint4 v0 = *reinterpret_cast<const uint4*>(Z + (size_t)i0 * 128 + c * 8);
        uint4 v1 = *reinterpret_cast<const uint4*>(Z + (size_t)i1 * 128 + c * 8);
        pair_flush(acc, v0, v1);
        j = jn; i0 = n0; i1 = n1;
    }
    if (j < deg) {
        uint4 v = *reinterpret_cast<const uint4*>(Z + (size_t)i0 * 128 + c * 8);
        add8h(acc, v);
    }

    __syncwarp();
    #pragma unroll
    for (int i = 0; i < 8; i++)
        acc[i] += __shfl_down_sync(0xffffffffu, acc[i], 16);

    if (g == 0) {
        float sc = 1.0f / ((float)cnt + 1.0f);
        float4 o0 = make_float4(fmaxf(acc[0] * sc, 0.f), fmaxf(acc[1] * sc, 0.f),
                                fmaxf(acc[2] * sc, 0.f), fmaxf(acc[3] * sc, 0.f));
        float4 o1 = make_float4(fmaxf(acc[4] * sc, 0.f), fmaxf(acc[5] * sc, 0.f),
                                fmaxf(acc[6] * sc, 0.f), fmaxf(acc[7] * sc, 0.f));
        float4* dst = reinterpret_cast<float4*>(H + (size_t)node * 128 + c * 8);
        dst[0] = o0;
        dst[1] = o1;
    }
}

// Final layer: 64-dim fp16 z, fp32 output. Warp = 4 groups of 8 lanes.
// Also re-zeroes g_count for graph-replay determinism.
__global__ void agg64_kernel(const __half* __restrict__ Z,
                             float* __restrict__ out) {
    int node = (blockIdx.x * blockDim.x + threadIdx.x) >> 5;
    if (node >= N_NODES) return;
    int lane = threadIdx.x & 31;
    int g = lane >> 3;
    int c = lane & 7;

    float acc[8];
    #pragma unroll
    for (int i = 0; i < 8; i++) acc[i] = 0.f;

    if (g == 0) {
        uint4 v = *reinterpret_cast<const uint4*>(Z + (size_t)node * 64 + c * 8);
        add8h(acc, v);
    }

    int cnt = g_count[node];
    int deg = cnt < CAP ? cnt : CAP;
    const int* sl = &g_slot[node * CAP];

    int j = g;
    int idx = (j < deg) ? sl[j] : 0;
    while (j < deg) {
        int jn = j + 4;
        int idxn = (jn < deg) ? sl[jn] : 0;
        uint4 v = *reinterpret_cast<const uint4*>(Z + (size_t)idx * 64 + c * 8);
        add8h(acc, v);
        j = jn; idx = idxn;
    }

    __syncwarp();
    #pragma unroll
    for (int i = 0; i < 8; i++)
        acc[i] += __shfl_down_sync(0xffffffffu, acc[i], 16);
    #pragma unroll
    for (int i = 0; i < 8; i++)
        acc[i] += __shfl_down_sync(0xffffffffu, acc[i], 8);

    if (lane < 8) {
        float sc = 1.0f / ((float)cnt + 1.0f);
        float4 o0 = make_float4(fmaxf(acc[0] * sc, 0.f), fmaxf(acc[1] * sc, 0.f),
                                fmaxf(acc[2] * sc, 0.f), fmaxf(acc[3] * sc, 0.f));
        float4 o1 = make_float4(fmaxf(acc[4] * sc, 0.f), fmaxf(acc[5] * sc, 0.f),
                                fmaxf(acc[6] * sc, 0.f), fmaxf(acc[7] * sc, 0.f));
        float4* dst = reinterpret_cast<float4*>(out + (size_t)node * 64 + c * 8);
        dst[0] = o0;
        dst[1] = o1;
    }
    if (lane == 0) g_count[node] = 0;   // reset for next launch / replay
}

// ---------------- launch ----------------
extern "C" void kernel_launch(void* const* d_in, const int* in_sizes, int n_in,
                              void* d_out, int out_size) {
    const float* x   = (const float*)d_in[0];
    const int*   ei  = (const int*)d_in[1];
    const float* W1  = (const float*)d_in[2];
    const float* W2  = (const float*)d_in[3];
    const float* W3  = (const float*)d_in[4];
    float*       out = (float*)d_out;

    const int* src = ei;
    const int* dst = ei + N_EDGES;

    __half* zh = nullptr;
    float*  h  = nullptr;
    uint2*  wp = nullptr;
    cudaGetSymbolAddress((void**)&zh, g_zh);
    cudaGetSymbolAddress((void**)&h,  g_h);
    cudaGetSymbolAddress((void**)&wp, g_wp);

    constexpr int SMEM_A = 2 * 128 * LDA * 2;   // 69632 bytes
    cudaFuncSetAttribute(mma_gemm<128>,
                         cudaFuncAttributeMaxDynamicSharedMemorySize, SMEM_A);
    cudaFuncSetAttribute(mma_gemm<64>,
                         cudaFuncAttributeMaxDynamicSharedMemorySize, SMEM_A);

    const int TPB = 256;
    const int gemm_blocks = (N_NODES + 127) / 128;             // 391
    const int agg_blocks  = (N_NODES * 32 + TPB - 1) / TPB;    // 6250
    const int fill_blocks = (N_EDGES / 2 + TPB - 1) / TPB;     // 1563

    fill_setup_kernel<<<fill_blocks, TPB>>>(src, dst, W1, W2, W3);

    // layer 1
    mma_gemm<128><<<gemm_blocks, 512, SMEM_A>>>(x, wp, zh);
    agg128_kernel<<<agg_blocks, TPB>>>(zh, h);
    // layer 2
    mma_gemm<128><<<gemm_blocks, 512, SMEM_A>>>(h, wp + 8192, zh);
    agg128_kernel<<<agg_blocks, TPB>>>(zh, h);
    // layer 3 (N=64), final relu + write out
    mma_gemm<64><<<gemm_blocks, 512, SMEM_A>>>(h, wp + 16384, zh);
    agg64_kernel<<<agg_blocks, TPB>>>(zh, out);
}

// round 15
// speedup vs baseline: 1.5417x; 1.3376x over previous
#include <cuda_runtime.h>
#include <cuda_bf16.h>
#include <cuda_fp16.h>
#include <cstdint>

#define N_NODES 50000
#define N_EDGES 800000
#define CAP 64
#define LDA 136

// ---------------- scratch (device globals; no allocation allowed) ----------
__device__ int    g_count[N_NODES];           // zero-init; re-zeroed by agg64
__device__ int    g_slot[N_NODES * CAP];
__device__ __half g_zh[N_NODES * 128];        // GEMM output, fp16
__device__ float  g_h[N_NODES * 128];         // agg output, fp32
// fragment-major packed split weights:
// g_wq[((layer_base + nt*8 + ks)*32 + lane] = uint4{hi(kp),hi(kp+4),lo(kp),lo(kp+4)}
// where n = nt*8 + (lane>>2), kp = ks*8 + (lane&3) in bf16-pair units.
// W1: 4096 uint4 | W2: 4096 | W3: 2048   (total 10240)
__device__ uint4  g_wq[10240];

// ---------------- small helpers ----------------
__device__ __forceinline__ uint32_t smem_u32(const void* p) {
    uint32_t a;
    asm("{ .reg .u64 t; cvta.to.shared.u64 t, %1; cvt.u32.u64 %0, t; }"
        : "=r"(a) : "l"(p));
    return a;
}

#define LDMATRIX_X4(r, addr) \
    asm volatile("ldmatrix.sync.aligned.m8n8.x4.shared.b16 {%0,%1,%2,%3}, [%4];" \
                 : "=r"((r)[0]), "=r"((r)[1]), "=r"((r)[2]), "=r"((r)[3]) \
                 : "r"(addr))

#define MMA_BF16(acc, a, b0, b1) \
    asm volatile("mma.sync.aligned.m16n8k16.row.col.f32.bf16.bf16.f32 " \
                 "{%0,%1,%2,%3}, {%4,%5,%6,%7}, {%8,%9}, {%0,%1,%2,%3};" \
                 : "+f"((acc)[0]), "+f"((acc)[1]), "+f"((acc)[2]), "+f"((acc)[3]) \
                 : "r"((a)[0]), "r"((a)[1]), "r"((a)[2]), "r"((a)[3]), \
                   "r"(b0), "r"(b1))

__device__ __forceinline__ uint32_t pack_bf162(float a, float b) {
    __nv_bfloat162 p;
    p.x = __float2bfloat16_rn(a);
    p.y = __float2bfloat16_rn(b);
    return *reinterpret_cast<uint32_t*>(&p);
}

// accumulate 8 fp16 values (as uint4) into 8 fp32 accumulators (exact)
__device__ __forceinline__ void add8h(float* acc, uint4 v) {
    const __half2* h = reinterpret_cast<const __half2*>(&v);
    #pragma unroll
    for (int i = 0; i < 4; i++) {
        float2 f = __half22float2(h[i]);
        acc[2 * i]     += f.x;
        acc[2 * i + 1] += f.y;
    }
}

// sum two fp16 rows pairwise in fp16 (1 rounding), flush to fp32
__device__ __forceinline__ void pair_flush(float* acc, uint4 a, uint4 b) {
    const __half2* pa = reinterpret_cast<const __half2*>(&a);
    const __half2* pb = reinterpret_cast<const __half2*>(&b);
    #pragma unroll
    for (int i = 0; i < 4; i++) {
        __half2 s = __hadd2(pa[i], pb[i]);
        float2 f = __half22float2(s);
        acc[2 * i]     += f.x;
        acc[2 * i + 1] += f.y;
    }
}

// ---------------- fill (2 edges/thread) + fragment-major split-W setup -----
__global__ void fill_setup_kernel(const int* __restrict__ src,
                                  const int* __restrict__ dst,
                                  const float* __restrict__ W1,
                                  const float* __restrict__ W2,
                                  const float* __restrict__ W3) {
    int t = blockIdx.x * blockDim.x + threadIdx.x;
    if (t < 10240) {
        const float* W;
        int rel;
        if (t < 4096)      { W = W1; rel = t; }
        else if (t < 8192) { W = W2; rel = t - 4096; }
        else               { W = W3; rel = t - 8192; }
        int nt   = rel >> 8;          // 8 ks * 32 lanes per nt
        int ks   = (rel >> 5) & 7;
        int lane = rel & 31;
        int n  = nt * 8 + (lane >> 2);
        int kp = ks * 8 + (lane & 3);
        const float* wr = W + n * 128;
        float a0 = wr[kp * 2],       a1 = wr[kp * 2 + 1];
        float b0 = wr[(kp + 4) * 2], b1 = wr[(kp + 4) * 2 + 1];
        __nv_bfloat16 ha0 = __float2bfloat16_rn(a0);
        __nv_bfloat16 ha1 = __float2bfloat16_rn(a1);
        __nv_bfloat16 hb0 = __float2bfloat16_rn(b0);
        __nv_bfloat16 hb1 = __float2bfloat16_rn(b1);
        uint4 q;
        __nv_bfloat162 ph; ph.x = ha0; ph.y = ha1;
        q.x = *reinterpret_cast<uint32_t*>(&ph);
        __nv_bfloat162 qh; qh.x = hb0; qh.y = hb1;
        q.y = *reinterpret_cast<uint32_t*>(&qh);
        q.z = pack_bf162(a0 - __bfloat162float(ha0), a1 - __bfloat162float(ha1));
        q.w = pack_bf162(b0 - __bfloat162float(hb0), b1 - __bfloat162float(hb1));
        g_wq[t] = q;
    }
    int e = t * 2;
    if (e < N_EDGES) {
        int2 s2 = *reinterpret_cast<const int2*>(src + e);
        int2 d2 = *reinterpret_cast<const int2*>(dst + e);
        int p = atomicAdd(&g_count[d2.x], 1);
        if (p < CAP) g_slot[d2.x * CAP + p] = s2.x;
        p = atomicAdd(&g_count[d2.y], 1);
        if (p < CAP) g_slot[d2.y * CAP + p] = s2.y;
    }
}

// ---------------- mma.sync split-bf16 GEMM: Zh[128-tile][N] = A @ W^T ------
// 512 threads = 16 warps; warp = (m16-tile wid>>1, column half wid&1).
// B fragments: ONE coalesced LDG.128 per (nt,ks) per warp (fragment-major).
// D = Ahi*Whi^T + Ahi*Wlo^T + Alo*Whi^T (fp32 acc), output fp16.
template <int N>
__global__ void __launch_bounds__(512, 2) mma_gemm(
    const float* __restrict__ A, const uint4* __restrict__ Wq,
    __half* __restrict__ Zh) {
    constexpr int NTW = N / 16;      // n-tiles per warp (half of N/8)
    extern __shared__ __nv_bfloat16 smem[];
    __nv_bfloat16* Ash = smem;
    __nv_bfloat16* Asl = smem + 128 * LDA;

    const int tid  = threadIdx.x;
    const int wid  = tid >> 5;
    const int lane = tid & 31;
    const int m0   = blockIdx.x * 128;

    for (int t = tid; t < 4096; t += 512) {
        int r = t >> 5;
        int c = (t & 31) << 2;
        int m = m0 + r;
        float4 v = make_float4(0.f, 0.f, 0.f, 0.f);
        if (m < N_NODES)
            v = *reinterpret_cast<const float4*>(A + (size_t)m * 128 + c);
        __nv_bfloat16 h0 = __float2bfloat16_rn(v.x);
        __nv_bfloat16 h1 = __float2bfloat16_rn(v.y);
        __nv_bfloat16 h2 = __float2bfloat16_rn(v.z);
        __nv_bfloat16 h3 = __float2bfloat16_rn(v.w);
        __nv_bfloat162 hp0; hp0.x = h0; hp0.y = h1;
        __nv_bfloat162 hp1; hp1.x = h2; hp1.y = h3;
        uint2 hv, lv;
        hv.x = *reinterpret_cast<uint32_t*>(&hp0);
        hv.y = *reinterpret_cast<uint32_t*>(&hp1);
        lv.x = pack_bf162(v.x - __bfloat162float(h0), v.y - __bfloat162float(h1));
        lv.y = pack_bf162(v.z - __bfloat162float(h2), v.w - __bfloat162float(h3));
        *reinterpret_cast<uint2*>(Ash + r * LDA + c) = hv;
        *reinterpret_cast<uint2*>(Asl + r * LDA + c) = lv;
    }
    __syncthreads();

    float acc[NTW][4];
    #pragma unroll
    for (int nt = 0; nt < NTW; nt++)
        #pragma unroll
        for (int i = 0; i < 4; i++) acc[nt][i] = 0.0f;

    const int wtile = wid >> 1;       // m16 tile 0..7
    const int chalf = wid & 1;        // column half 0..1
    const int lrow = lane & 15;
    const int kgrp = (lane >> 4) * 8;

    #pragma unroll
    for (int ks = 0; ks < 8; ks++) {
        const int k0 = ks * 16;
        uint32_t ah[4], al[4];
        uint32_t ad = smem_u32(Ash + (wtile * 16 + lrow) * LDA + k0 + kgrp);
        LDMATRIX_X4(ah, ad);
        uint32_t bd = smem_u32(Asl + (wtile * 16 + lrow) * LDA + k0 + kgrp);
        LDMATRIX_X4(al, bd);
        #pragma unroll
        for (int nt = 0; nt < NTW; nt++) {
            int ntg = chalf * NTW + nt;
            uint4 q = Wq[(size_t)((ntg * 8 + ks) * 32) + lane];
            MMA_BF16(acc[nt], ah, q.x, q.y);
            MMA_BF16(acc[nt], ah, q.z, q.w);
            MMA_BF16(acc[nt], al, q.x, q.y);
        }
    }

    int r0 = m0 + wtile * 16 + (lane >> 2);
    #pragma unroll
    for (int nt = 0; nt < NTW; nt++) {
        int col = (chalf * NTW + nt) * 8 + (lane & 3) * 2;
        if (r0 < N_NODES) {
            __half2 hv = __floats2half2_rn(acc[nt][0], acc[nt][1]);
            *reinterpret_cast<__half2*>(Zh + (size_t)r0 * N + col) = hv;
        }
        if (r0 + 8 < N_NODES) {
            __half2 hv = __floats2half2_rn(acc[nt][2], acc[nt][3]);
            *reinterpret_cast<__half2*>(Zh + (size_t)(r0 + 8) * N + col) = hv;
        }
    }
}

// ---------------- gather + self + inv-scale + relu (fp16 z) ----------------
// Rolling index prefetch, two rows in flight, pairwise fp16 add (1 rounding)
// before the fp32 flush.
__global__ void agg128_kernel(const __half* __restrict__ Z,
                              float* __restrict__ H) {
    int node = (blockIdx.x * blockDim.x + threadIdx.x) >> 5;
    if (node >= N_NODES) return;
    int lane = threadIdx.x & 31;
    int g = lane >> 4;
    int c = lane & 15;

    float acc[8];
    #pragma unroll
    for (int i = 0; i < 8; i++) acc[i] = 0.f;

    if (g == 0) {
        uint4 v = *reinterpret_cast<const uint4*>(Z + (size_t)node * 128 + c * 8);
        add8h(acc, v);
    }

    int cnt = g_count[node];
    int deg = cnt < CAP ? cnt : CAP;
    const int* sl = &g_slot[node * CAP];

    int j = g;
    int i0 = (j < deg)     ? sl[j]     : 0;
    int i1 = (j + 2 < deg) ? sl[j + 2] : 0;
    while (j + 2 < deg) {
        int jn = j + 4;
        int n0 = (jn < deg)     ? sl[jn]     : 0;
        int n1 = (jn + 2 < deg) ? sl[jn + 2] : 0;
        uint4 v0 = *reinterpret_cast<const uint4*>(Z + (size_t)i0 * 128 + c * 8);
        uint4 v1 = *reinterpret_cast<const uint4*>(Z + (size_t)i1 * 128 + c * 8);
        pair_flush(acc, v0, v1);
        j = jn; i0 = n0; i1 = n1;
    }
    if (j < deg) {
        uint4 v = *reinterpret_cast<const uint4*>(Z + (size_t)i0 * 128 + c * 8);
        add8h(acc, v);
    }

    __syncwarp();
    #pragma unroll
    for (int i = 0; i < 8; i++)
        acc[i] += __shfl_down_sync(0xffffffffu, acc[i], 16);

    if (g == 0) {
        float sc = 1.0f / ((float)cnt + 1.0f);
        float4 o0 = make_float4(fmaxf(acc[0] * sc, 0.f), fmaxf(acc[1] * sc, 0.f),
                                fmaxf(acc[2] * sc, 0.f), fmaxf(acc[3] * sc, 0.f));
        float4 o1 = make_float4(fmaxf(acc[4] * sc, 0.f), fmaxf(acc[5] * sc, 0.f),
                                fmaxf(acc[6] * sc, 0.f), fmaxf(acc[7] * sc, 0.f));
        float4* dst = reinterpret_cast<float4*>(H + (size_t)node * 128 + c * 8);
        dst[0] = o0;
        dst[1] = o1;
    }
}

// Final layer: 64-dim fp16 z, fp32 output. Warp = 4 groups of 8 lanes.
// Also re-zeroes g_count for graph-replay determinism.
__global__ void agg64_kernel(const __half* __restrict__ Z,
                             float* __restrict__ out) {
    int node = (blockIdx.x * blockDim.x + threadIdx.x) >> 5;
    if (node >= N_NODES) return;
    int lane = threadIdx.x & 31;
    int g = lane >> 3;
    int c = lane & 7;

    float acc[8];
    #pragma unroll
    for (int i = 0; i < 8; i++) acc[i] = 0.f;

    if (g == 0) {
        uint4 v = *reinterpret_cast<const uint4*>(Z + (size_t)node * 64 + c * 8);
        add8h(acc, v);
    }

    int cnt = g_count[node];
    int deg = cnt < CAP ? cnt : CAP;
    const int* sl = &g_slot[node * CAP];

    int j = g;
    int idx = (j < deg) ? sl[j] : 0;
    while (j < deg) {
        int jn = j + 4;
        int idxn = (jn < deg) ? sl[jn] : 0;
        uint4 v = *reinterpret_cast<const uint4*>(Z + (size_t)idx * 64 + c * 8);
        add8h(acc, v);
        j = jn; idx = idxn;
    }

    __syncwarp();
    #pragma unroll
    for (int i = 0; i < 8; i++)
        acc[i] += __shfl_down_sync(0xffffffffu, acc[i], 16);
    #pragma unroll
    for (int i = 0; i < 8; i++)
        acc[i] += __shfl_down_sync(0xffffffffu, acc[i], 8);

    if (lane < 8) {
        float sc = 1.0f / ((float)cnt + 1.0f);
        float4 o0 = make_float4(fmaxf(acc[0] * sc, 0.f), fmaxf(acc[1] * sc, 0.f),
                                fmaxf(acc[2] * sc, 0.f), fmaxf(acc[3] * sc, 0.f));
        float4 o1 = make_float4(fmaxf(acc[4] * sc, 0.f), fmaxf(acc[5] * sc, 0.f),
                                fmaxf(acc[6] * sc, 0.f), fmaxf(acc[7] * sc, 0.f));
        float4* dst = reinterpret_cast<float4*>(out + (size_t)node * 64 + c * 8);
        dst[0] = o0;
        dst[1] = o1;
    }
    if (lane == 0) g_count[node] = 0;   // reset for next launch / replay
}

// ---------------- launch ----------------
extern "C" void kernel_launch(void* const* d_in, const int* in_sizes, int n_in,
                              void* d_out, int out_size) {
    const float* x   = (const float*)d_in[0];
    const int*   ei  = (const int*)d_in[1];
    const float* W1  = (const float*)d_in[2];
    const float* W2  = (const float*)d_in[3];
    const float* W3  = (const float*)d_in[4];
    float*       out = (float*)d_out;

    const int* src = ei;
    const int* dst = ei + N_EDGES;

    __half* zh = nullptr;
    float*  h  = nullptr;
    uint4*  wq = nullptr;
    cudaGetSymbolAddress((void**)&zh, g_zh);
    cudaGetSymbolAddress((void**)&h,  g_h);
    cudaGetSymbolAddress((void**)&wq, g_wq);

    constexpr int SMEM_A = 2 * 128 * LDA * 2;   // 69632 bytes
    cudaFuncSetAttribute(mma_gemm<128>,
                         cudaFuncAttributeMaxDynamicSharedMemorySize, SMEM_A);
    cudaFuncSetAttribute(mma_gemm<64>,
                         cudaFuncAttributeMaxDynamicSharedMemorySize, SMEM_A);

    const int TPB = 256;
    const int gemm_blocks = (N_NODES + 127) / 128;             // 391
    const int agg_blocks  = (N_NODES * 32 + TPB - 1) / TPB;    // 6250
    const int fill_blocks = (N_EDGES / 2 + TPB - 1) / TPB;     // 1563

    fill_setup_kernel<<<fill_blocks, TPB>>>(src, dst, W1, W2, W3);

    // layer 1
    mma_gemm<128><<<gemm_blocks, 512, SMEM_A>>>(x, wq, zh);
    agg128_kernel<<<agg_blocks, TPB>>>(zh, h);
    // layer 2
    mma_gemm<128><<<gemm_blocks, 512, SMEM_A>>>(h, wq + 4096, zh);
    agg128_kernel<<<agg_blocks, TPB>>>(zh, h);
    // layer 3 (N=64), final relu + write out
    mma_gemm<64><<<gemm_blocks, 512, SMEM_A>>>(h, wq + 8192, zh);
    agg64_kernel<<<agg_blocks, TPB>>>(zh, out);
}

// round 16
// speedup vs baseline: 1.8992x; 1.2319x over previous
#include <cuda_runtime.h>
#include <cuda_fp16.h>
#include <cstdint>

#define N_NODES 50000
#define N_EDGES 800000
#define CAP 64
#define LDA 136

// ---------------- scratch (device globals; no allocation allowed) ----------
__device__ int    g_count[N_NODES];           // zero-init; re-zeroed by agg64
__device__ int    g_slot[N_NODES * CAP];
__device__ __half g_zh[N_NODES * 128];        // GEMM output z, fp16
__device__ __half g_hh[N_NODES * 128];        // agg output h, fp16
// fragment-major fp16 weights, ks-pairs packed:
// g_wf[(base + nt*4 + ksp)*32 + lane] = uint4{
//   fp16x2 W[n][k0..k0+1], W[n][k0+8..+9], W[n][k0+16..+17], W[n][k0+24..+25]}
// with n = nt*8 + (lane>>2), k0 = ksp*32 + (lane&3)*2.
// W1: 2048 uint4 | W2: 2048 | W3: 1024   (total 5120)
__device__ uint4  g_wf[5120];

// ---------------- small helpers ----------------
__device__ __forceinline__ uint32_t smem_u32(const void* p) {
    uint32_t a;
    asm("{ .reg .u64 t; cvta.to.shared.u64 t, %1; cvt.u32.u64 %0, t; }"
        : "=r"(a) : "l"(p));
    return a;
}

#define LDMATRIX_X4(r, addr) \
    asm volatile("ldmatrix.sync.aligned.m8n8.x4.shared.b16 {%0,%1,%2,%3}, [%4];" \
                 : "=r"((r)[0]), "=r"((r)[1]), "=r"((r)[2]), "=r"((r)[3]) \
                 : "r"(addr))

#define MMA_FP16(acc, a, b0, b1) \
    asm volatile("mma.sync.aligned.m16n8k16.row.col.f32.f16.f16.f32 " \
                 "{%0,%1,%2,%3}, {%4,%5,%6,%7}, {%8,%9}, {%0,%1,%2,%3};" \
                 : "+f"((acc)[0]), "+f"((acc)[1]), "+f"((acc)[2]), "+f"((acc)[3]) \
                 : "r"((a)[0]), "r"((a)[1]), "r"((a)[2]), "r"((a)[3]), \
                   "r"(b0), "r"(b1))

__device__ __forceinline__ uint32_t pack_h2(float a, float b) {
    __half2 p = __floats2half2_rn(a, b);
    return *reinterpret_cast<uint32_t*>(&p);
}

// accumulate 8 fp16 values (as uint4) into 8 fp32 accumulators (exact)
__device__ __forceinline__ void add8h(float* acc, uint4 v) {
    const __half2* h = reinterpret_cast<const __half2*>(&v);
    #pragma unroll
    for (int i = 0; i < 4; i++) {
        float2 f = __half22float2(h[i]);
        acc[2 * i]     += f.x;
        acc[2 * i + 1] += f.y;
    }
}

// sum two fp16 rows pairwise in fp16 (1 rounding), flush to fp32
__device__ __forceinline__ void pair_flush(float* acc, uint4 a, uint4 b) {
    const __half2* pa = reinterpret_cast<const __half2*>(&a);
    const __half2* pb = reinterpret_cast<const __half2*>(&b);
    #pragma unroll
    for (int i = 0; i < 4; i++) {
        __half2 s = __hadd2(pa[i], pb[i]);
        float2 f = __half22float2(s);
        acc[2 * i]     += f.x;
        acc[2 * i + 1] += f.y;
    }
}

// ---------------- fill (2 edges/thread) + fragment-major fp16 W setup ------
__global__ void fill_setup_kernel(const int* __restrict__ src,
                                  const int* __restrict__ dst,
                                  const float* __restrict__ W1,
                                  const float* __restrict__ W2,
                                  const float* __restrict__ W3) {
    int t = blockIdx.x * blockDim.x + threadIdx.x;
    if (t < 5120) {
        const float* W;
        int rel;
        if (t < 2048)      { W = W1; rel = t; }
        else if (t < 4096) { W = W2; rel = t - 2048; }
        else               { W = W3; rel = t - 4096; }
        int nt   = rel >> 7;          // 4 ksp * 32 lanes per nt
        int ksp  = (rel >> 5) & 3;
        int lane = rel & 31;
        int n  = nt * 8 + (lane >> 2);
        int k0 = ksp * 32 + (lane & 3) * 2;
        const float* wr = W + n * 128;
        uint4 q;
        q.x = pack_h2(wr[k0],      wr[k0 + 1]);
        q.y = pack_h2(wr[k0 + 8],  wr[k0 + 9]);
        q.z = pack_h2(wr[k0 + 16], wr[k0 + 17]);
        q.w = pack_h2(wr[k0 + 24], wr[k0 + 25]);
        g_wf[t] = q;
    }
    int e = t * 2;
    if (e < N_EDGES) {
        int2 s2 = *reinterpret_cast<const int2*>(src + e);
        int2 d2 = *reinterpret_cast<const int2*>(dst + e);
        int p = atomicAdd(&g_count[d2.x], 1);
        if (p < CAP) g_slot[d2.x * CAP + p] = s2.x;
        p = atomicAdd(&g_count[d2.y], 1);
        if (p < CAP) g_slot[d2.y * CAP + p] = s2.y;
    }
}

// ---------------- fp16 mma.sync GEMM: Zh[128-tile][N] = A @ W^T ------------
// 512 threads = 16 warps; warp = (m16-tile wid>>1, column half wid&1).
// A staged as fp16 in smem (fp32 input converted, fp16 input copied).
// B fragments: one coalesced LDG.128 per (nt, ks-pair) per warp.
template <int N, bool FP32IN>
__global__ void __launch_bounds__(512, 2) mma_gemm(
    const void* __restrict__ Ain, const uint4* __restrict__ Wf,
    __half* __restrict__ Zh) {
    constexpr int NTW = N / 16;      // n-tiles per warp (half of N/8)
    extern __shared__ __half smem[];
    __half* Ash = smem;              // [128][LDA] fp16

    const int tid  = threadIdx.x;
    const int wid  = tid >> 5;
    const int lane = tid & 31;
    const int m0   = blockIdx.x * 128;

    if (FP32IN) {
        const float* A = (const float*)Ain;
        for (int t = tid; t < 4096; t += 512) {
            int r = t >> 5;
            int c = (t & 31) << 2;
            int m = m0 + r;
            float4 v = make_float4(0.f, 0.f, 0.f, 0.f);
            if (m < N_NODES)
                v = *reinterpret_cast<const float4*>(A + (size_t)m * 128 + c);
            uint2 hv;
            hv.x = pack_h2(v.x, v.y);
            hv.y = pack_h2(v.z, v.w);
            *reinterpret_cast<uint2*>(Ash + r * LDA + c) = hv;
        }
    } else {
        const __half* A = (const __half*)Ain;
        for (int t = tid; t < 2048; t += 512) {
            int r = t >> 4;
            int c = (t & 15) << 3;
            int m = m0 + r;
            uint4 v = make_uint4(0u, 0u, 0u, 0u);
            if (m < N_NODES)
                v = *reinterpret_cast<const uint4*>(A + (size_t)m * 128 + c);
            *reinterpret_cast<uint4*>(Ash + r * LDA + c) = v;
        }
    }
    __syncthreads();

    float acc[NTW][4];
    #pragma unroll
    for (int nt = 0; nt < NTW; nt++)
        #pragma unroll
        for (int i = 0; i < 4; i++) acc[nt][i] = 0.0f;

    const int wtile = wid >> 1;       // m16 tile 0..7
    const int chalf = wid & 1;        // column half 0..1
    const int lrow = lane & 15;
    const int kgrp = (lane >> 4) * 8;

    #pragma unroll
    for (int ksp = 0; ksp < 4; ksp++) {
        const int k0 = ksp * 32;
        uint32_t a0[4], a1[4];
        uint32_t ad0 = smem_u32(Ash + (wtile * 16 + lrow) * LDA + k0 + kgrp);
        LDMATRIX_X4(a0, ad0);
        uint32_t ad1 = smem_u32(Ash + (wtile * 16 + lrow) * LDA + k0 + 16 + kgrp);
        LDMATRIX_X4(a1, ad1);
        #pragma unroll
        for (int nt = 0; nt < NTW; nt++) {
            int ntg = chalf * NTW + nt;
            uint4 q = Wf[(size_t)((ntg * 4 + ksp) * 32) + lane];
            MMA_FP16(acc[nt], a0, q.x, q.y);
            MMA_FP16(acc[nt], a1, q.z, q.w);
        }
    }

    int r0 = m0 + wtile * 16 + (lane >> 2);
    #pragma unroll
    for (int nt = 0; nt < NTW; nt++) {
        int col = (chalf * NTW + nt) * 8 + (lane & 3) * 2;
        if (r0 < N_NODES) {
            __half2 hv = __floats2half2_rn(acc[nt][0], acc[nt][1]);
            *reinterpret_cast<__half2*>(Zh + (size_t)r0 * N + col) = hv;
        }
        if (r0 + 8 < N_NODES) {
            __half2 hv = __floats2half2_rn(acc[nt][2], acc[nt][3]);
            *reinterpret_cast<__half2*>(Zh + (size_t)(r0 + 8) * N + col) = hv;
        }
    }
}

// ---------------- gather + self + inv-scale + relu (fp16 z -> fp16 h) ------
// Rolling index prefetch, two rows in flight, pairwise fp16 add (1 rounding)
// before the fp32 flush.
__global__ void agg128_kernel(const __half* __restrict__ Z,
                              __half* __restrict__ H) {
    int node = (blockIdx.x * blockDim.x + threadIdx.x) >> 5;
    if (node >= N_NODES) return;
    int lane = threadIdx.x & 31;
    int g = lane >> 4;
    int c = lane & 15;

    float acc[8];
    #pragma unroll
    for (int i = 0; i < 8; i++) acc[i] = 0.f;

    if (g == 0) {
        uint4 v = *reinterpret_cast<const uint4*>(Z + (size_t)node * 128 + c * 8);
        add8h(acc, v);
    }

    int cnt = g_count[node];
    int deg = cnt < CAP ? cnt : CAP;
    const int* sl = &g_slot[node * CAP];

    int j = g;
    int i0 = (j < deg)     ? sl[j]     : 0;
    int i1 = (j + 2 < deg) ? sl[j + 2] : 0;
    while (j + 2 < deg) {
        int jn = j + 4;
        int n0 = (jn < deg)     ? sl[jn]     : 0;
        int n1 = (jn + 2 < deg) ? sl[jn + 2] : 0;
        uint4 v0 = *reinterpret_cast<const uint4*>(Z + (size_t)i0 * 128 + c * 8);
        uint4 v1 = *reinterpret_cast<const uint4*>(Z + (size_t)i1 * 128 + c * 8);
        pair_flush(acc, v0, v1);
        j = jn; i0 = n0; i1 = n1;
    }
    if (j < deg) {
        uint4 v = *reinterpret_cast<const uint4*>(Z + (size_t)i0 * 128 + c * 8);
        add8h(acc, v);
    }

    __syncwarp();
    #pragma unroll
    for (int i = 0; i < 8; i++)
        acc[i] += __shfl_down_sync(0xffffffffu, acc[i], 16);

    if (g == 0) {
        float sc = 1.0f / ((float)cnt + 1.0f);
        uint4 o;
        o.x = pack_h2(fmaxf(acc[0] * sc, 0.f), fmaxf(acc[1] * sc, 0.f));
        o.y = pack_h2(fmaxf(acc[2] * sc, 0.f), fmaxf(acc[3] * sc, 0.f));
        o.z = pack_h2(fmaxf(acc[4] * sc, 0.f), fmaxf(acc[5] * sc, 0.f));
        o.w = pack_h2(fmaxf(acc[6] * sc, 0.f), fmaxf(acc[7] * sc, 0.f));
        *reinterpret_cast<uint4*>(H + (size_t)node * 128 + c * 8) = o;
    }
}

// Final layer: 64-dim fp16 z, fp32 output. Warp = 4 groups of 8 lanes.
// Also re-zeroes g_count for graph-replay determinism.
__global__ void agg64_kernel(const __half* __restrict__ Z,
                             float* __restrict__ out) {
    int node = (blockIdx.x * blockDim.x + threadIdx.x) >> 5;
    if (node >= N_NODES) return;
    int lane = threadIdx.x & 31;
    int g = lane >> 3;
    int c = lane & 7;

    float acc[8];
    #pragma unroll
    for (int i = 0; i < 8; i++) acc[i] = 0.f;

    if (g == 0) {
        uint4 v = *reinterpret_cast<const uint4*>(Z + (size_t)node * 64 + c * 8);
        add8h(acc, v);
    }

    int cnt = g_count[node];
    int deg = cnt < CAP ? cnt : CAP;
    const int* sl = &g_slot[node * CAP];

    int j = g;
    int idx = (j < deg) ? sl[j] : 0;
    while (j < deg) {
        int jn = j + 4;
        int idxn = (jn < deg) ? sl[jn] : 0;
        uint4 v = *reinterpret_cast<const uint4*>(Z + (size_t)idx * 64 + c * 8);
        add8h(acc, v);
        j = jn; idx = idxn;
    }

    __syncwarp();
    #pragma unroll
    for (int i = 0; i < 8; i++)
        acc[i] += __shfl_down_sync(0xffffffffu, acc[i], 16);
    #pragma unroll
    for (int i = 0; i < 8; i++)
        acc[i] += __shfl_down_sync(0xffffffffu, acc[i], 8);

    if (lane < 8) {
        float sc = 1.0f / ((float)cnt + 1.0f);
        float4 o0 = make_float4(fmaxf(acc[0] * sc, 0.f), fmaxf(acc[1] * sc, 0.f),
                                fmaxf(acc[2] * sc, 0.f), fmaxf(acc[3] * sc, 0.f));
        float4 o1 = make_float4(fmaxf(acc[4] * sc, 0.f), fmaxf(acc[5] * sc, 0.f),
                                fmaxf(acc[6] * sc, 0.f), fmaxf(acc[7] * sc, 0.f));
        float4* dst = reinterpret_cast<float4*>(out + (size_t)node * 64 + c * 8);
        dst[0] = o0;
        dst[1] = o1;
    }
    if (lane == 0) g_count[node] = 0;   // reset for next launch / replay
}

// ---------------- launch ----------------
extern "C" void kernel_launch(void* const* d_in, const int* in_sizes, int n_in,
                              void* d_out, int out_size) {
    const float* x   = (const float*)d_in[0];
    const int*   ei  = (const int*)d_in[1];
    const float* W1  = (const float*)d_in[2];
    const float* W2  = (const float*)d_in[3];
    const float* W3  = (const float*)d_in[4];
    float*       out = (float*)d_out;

    const int* src = ei;
    const int* dst = ei + N_EDGES;

    __half* zh = nullptr;
    __half* hh = nullptr;
    uint4*  wf = nullptr;
    cudaGetSymbolAddress((void**)&zh, g_zh);
    cudaGetSymbolAddress((void**)&hh, g_hh);
    cudaGetSymbolAddress((void**)&wf, g_wf);

    constexpr int SMEM_A = 128 * LDA * 2;   // 34816 bytes (fp16 tile)
    cudaFuncSetAttribute((const void*)mma_gemm<128, true>,
                         cudaFuncAttributeMaxDynamicSharedMemorySize, SMEM_A);
    cudaFuncSetAttribute((const void*)mma_gemm<128, false>,
                         cudaFuncAttributeMaxDynamicSharedMemorySize, SMEM_A);
    cudaFuncSetAttribute((const void*)mma_gemm<64, false>,
                         cudaFuncAttributeMaxDynamicSharedMemorySize, SMEM_A);

    const int TPB = 256;
    const int gemm_blocks = (N_NODES + 127) / 128;             // 391
    const int agg_blocks  = (N_NODES * 32 + TPB - 1) / TPB;    // 6250
    const int fill_blocks = (N_EDGES / 2 + TPB - 1) / TPB;     // 1563

    fill_setup_kernel<<<fill_blocks, TPB>>>(src, dst, W1, W2, W3);

    // layer 1: z = x @ W1^T (fp32 input)
    mma_gemm<128, true><<<gemm_blocks, 512, SMEM_A>>>(x, wf, zh);
    agg128_kernel<<<agg_blocks, TPB>>>(zh, hh);
    // layer 2: z = h @ W2^T (fp16 input)
    mma_gemm<128, false><<<gemm_blocks, 512, SMEM_A>>>(hh, wf + 2048, zh);
    agg128_kernel<<<agg_blocks, TPB>>>(zh, hh);
    // layer 3 (N=64): z = h @ W3^T
    mma_gemm<64, false><<<gemm_blocks, 512, SMEM_A>>>(hh, wf + 4096, zh);
    agg64_kernel<<<agg_blocks, TPB>>>(zh, out);
}